// round 3
// baseline (speedup 1.0000x reference)
#include <cuda_runtime.h>
#include <math.h>

// Problem constants
#define BSZ 16384
#define EDIM 256
#define HDIM 1024
#define NLAYER 8
#define NACT 256
#define NK 4

// Scratch (device globals — no allocation allowed)
__device__ float g_x[(size_t)BSZ * HDIM];   // 64 MB
__device__ float g_y[(size_t)BSZ * HDIM];   // 64 MB
__device__ float g_z[(size_t)BSZ * EDIM];   // 16 MB

// ---------------------------------------------------------------------------
// SGEMM: C[M,N] = act(A[M,K] @ W[K,N] + bias[N]) ; act = ReLU if relu!=0
// Tiles: 128x128x16, 256 threads, 8x8 per-thread microtile.
// All dims used here are multiples of the tile sizes -> no bounds checks.
// ---------------------------------------------------------------------------
#define BM 128
#define BN 128
#define BK 16
#define TM 8
#define TN 8

__global__ __launch_bounds__(256)
void sgemm_bias_act(const float* __restrict__ A, const float* __restrict__ W,
                    const float* __restrict__ bias, float* __restrict__ C,
                    int M, int N, int K, int relu)
{
    __shared__ float As[BK][BM];
    __shared__ float Bs[BK][BN];

    const int tid = threadIdx.x;
    const int m0 = blockIdx.y * BM;
    const int n0 = blockIdx.x * BN;
    const int tx = tid & 15;   // 16 cols of threads
    const int ty = tid >> 4;   // 16 rows of threads

    float acc[TM][TN];
#pragma unroll
    for (int i = 0; i < TM; i++)
#pragma unroll
        for (int j = 0; j < TN; j++) acc[i][j] = 0.f;

    for (int k0 = 0; k0 < K; k0 += BK) {
        // Load A tile 128x16 (transpose into As[k][m])
#pragma unroll
        for (int i = 0; i < 2; i++) {
            int idx = tid + i * 256;           // 0..511
            int r   = idx >> 2;                // 0..127
            int c4  = (idx & 3) << 2;          // 0,4,8,12
            float4 v = *(const float4*)&A[(size_t)(m0 + r) * K + k0 + c4];
            As[c4 + 0][r] = v.x;
            As[c4 + 1][r] = v.y;
            As[c4 + 2][r] = v.z;
            As[c4 + 3][r] = v.w;
        }
        // Load B tile 16x128 (direct)
#pragma unroll
        for (int i = 0; i < 2; i++) {
            int idx = tid + i * 256;           // 0..511
            int r   = idx >> 5;                // 0..15
            int c4  = (idx & 31) << 2;         // 0..124
            *(float4*)&Bs[r][c4] =
                *(const float4*)&W[(size_t)(k0 + r) * N + n0 + c4];
        }
        __syncthreads();

#pragma unroll
        for (int k = 0; k < BK; k++) {
            float a[TM], b[TN];
            *(float4*)&a[0] = *(const float4*)&As[k][ty * TM];
            *(float4*)&a[4] = *(const float4*)&As[k][ty * TM + 4];
            *(float4*)&b[0] = *(const float4*)&Bs[k][tx * TN];
            *(float4*)&b[4] = *(const float4*)&Bs[k][tx * TN + 4];
#pragma unroll
            for (int i = 0; i < TM; i++)
#pragma unroll
                for (int j = 0; j < TN; j++)
                    acc[i][j] = fmaf(a[i], b[j], acc[i][j]);
        }
        __syncthreads();
    }

    // Epilogue: +bias, optional ReLU, store
    float bfrag[TN];
#pragma unroll
    for (int j = 0; j < TN; j += 4)
        *(float4*)&bfrag[j] = *(const float4*)&bias[n0 + tx * TN + j];

#pragma unroll
    for (int i = 0; i < TM; i++) {
        size_t row = (size_t)(m0 + ty * TM + i);
#pragma unroll
        for (int j = 0; j < TN; j += 4) {
            float4 v;
            v.x = acc[i][j + 0] + bfrag[j + 0];
            v.y = acc[i][j + 1] + bfrag[j + 1];
            v.z = acc[i][j + 2] + bfrag[j + 2];
            v.w = acc[i][j + 3] + bfrag[j + 3];
            if (relu) {
                v.x = fmaxf(v.x, 0.f); v.y = fmaxf(v.y, 0.f);
                v.z = fmaxf(v.z, 0.f); v.w = fmaxf(v.w, 0.f);
            }
            *(float4*)&C[row * N + n0 + tx * TN + j] = v;
        }
    }
}

// ---------------------------------------------------------------------------
// LayerNorm over H=1024, one block (256 threads) per row.
// out = (hasRes ? res : 0) + LN(pre) * g + beta
// ---------------------------------------------------------------------------
__global__ __launch_bounds__(256)
void ln_res(const float* __restrict__ pre, const float* __restrict__ res,
            const float* __restrict__ g, const float* __restrict__ beta,
            float* __restrict__ out, int hasRes)
{
    const size_t row = blockIdx.x;
    const int c = threadIdx.x << 2;   // 4 elems/thread

    float4 v = *(const float4*)&pre[row * HDIM + c];
    float s  = v.x + v.y + v.z + v.w;
    float ss = v.x * v.x + v.y * v.y + v.z * v.z + v.w * v.w;

#pragma unroll
    for (int o = 16; o; o >>= 1) {
        s  += __shfl_xor_sync(0xFFFFFFFFu, s, o);
        ss += __shfl_xor_sync(0xFFFFFFFFu, ss, o);
    }
    __shared__ float sh_s[8], sh_ss[8];
    const int warp = threadIdx.x >> 5, lane = threadIdx.x & 31;
    if (lane == 0) { sh_s[warp] = s; sh_ss[warp] = ss; }
    __syncthreads();
    float ts = 0.f, tss = 0.f;
#pragma unroll
    for (int w = 0; w < 8; w++) { ts += sh_s[w]; tss += sh_ss[w]; }

    const float mean = ts * (1.0f / HDIM);
    const float var  = tss * (1.0f / HDIM) - mean * mean;
    const float inv  = rsqrtf(var + 1e-5f);

    float4 gg = *(const float4*)&g[c];
    float4 bb = *(const float4*)&beta[c];
    float4 o4;
    o4.x = (v.x - mean) * inv * gg.x + bb.x;
    o4.y = (v.y - mean) * inv * gg.y + bb.y;
    o4.z = (v.z - mean) * inv * gg.z + bb.z;
    o4.w = (v.w - mean) * inv * gg.w + bb.w;
    if (hasRes) {
        float4 r = *(const float4*)&res[row * HDIM + c];
        o4.x += r.x; o4.y += r.y; o4.z += r.z; o4.w += r.w;
    }
    *(float4*)&out[row * HDIM + c] = o4;
}

// ---------------------------------------------------------------------------
// logits[b,a] = dot(z[b,:], AE[b,a,:]) ; -inf where sum(idx[b,a,:])==0
// One block per batch row; one warp per action (round-robin).
// ---------------------------------------------------------------------------
__global__ __launch_bounds__(256)
void logits_k(const float* __restrict__ z, const float* __restrict__ AE,
              const int* __restrict__ idx, float* __restrict__ out)
{
    const size_t b = blockIdx.x;
    __shared__ float zs[EDIM];
    zs[threadIdx.x] = z[b * EDIM + threadIdx.x];
    __syncthreads();

    const int warp = threadIdx.x >> 5, lane = threadIdx.x & 31;
    const float* aeb = AE + b * (size_t)NACT * EDIM;
    const int c = lane << 2;

    for (int a = warp; a < NACT; a += 8) {
        const float* r = aeb + (size_t)a * EDIM;
        float4 x0 = *(const float4*)&r[c];
        float4 x1 = *(const float4*)&r[128 + c];
        float acc = x0.x * zs[c]       + x0.y * zs[c + 1]
                  + x0.z * zs[c + 2]   + x0.w * zs[c + 3]
                  + x1.x * zs[128 + c]     + x1.y * zs[128 + c + 1]
                  + x1.z * zs[128 + c + 2] + x1.w * zs[128 + c + 3];
#pragma unroll
        for (int o = 16; o; o >>= 1)
            acc += __shfl_xor_sync(0xFFFFFFFFu, acc, o);
        if (lane == 0) {
            int4 ii = *(const int4*)&idx[(b * NACT + a) * NK];
            int sum = ii.x + ii.y + ii.z + ii.w;
            out[b * NACT + a] = (sum == 0) ? -INFINITY : acc;
        }
    }
}

// ---------------------------------------------------------------------------
// kernel_launch
// Input order: obs, AE, idx, w0, b0, g0, beta0, Wb, bb, gb, betab, w1, b1, w2, b2
// ---------------------------------------------------------------------------
extern "C" void kernel_launch(void* const* d_in, const int* in_sizes, int n_in,
                              void* d_out, int out_size)
{
    const float* obs  = (const float*)d_in[0];
    const float* AE   = (const float*)d_in[1];
    const int*   idx  = (const int*)  d_in[2];
    const float* w0   = (const float*)d_in[3];
    const float* b0   = (const float*)d_in[4];
    const float* g0   = (const float*)d_in[5];
    const float* bt0  = (const float*)d_in[6];
    const float* Wb   = (const float*)d_in[7];
    const float* bb   = (const float*)d_in[8];
    const float* gb   = (const float*)d_in[9];
    const float* btb  = (const float*)d_in[10];
    const float* w1   = (const float*)d_in[11];
    const float* b1   = (const float*)d_in[12];
    const float* w2   = (const float*)d_in[13];
    const float* b2   = (const float*)d_in[14];
    float* out = (float*)d_out;

    void *px, *py, *pz;
    cudaGetSymbolAddress(&px, g_x);
    cudaGetSymbolAddress(&py, g_y);
    cudaGetSymbolAddress(&pz, g_z);
    float* gx = (float*)px;
    float* gy = (float*)py;
    float* gz = (float*)pz;

    const dim3 blk(256);
    const dim3 gH(HDIM / BN, BSZ / BM);   // (8, 128)
    const dim3 gE(EDIM / BN, BSZ / BM);   // (2, 128)

    // obs_transform: y = ReLU(obs @ w0 + b0); x = LN(y)
    sgemm_bias_act<<<gH, blk>>>(obs, w0, b0, gy, BSZ, HDIM, EDIM, 1);
    ln_res<<<BSZ, blk>>>(gy, nullptr, g0, bt0, gx, 0);

    // 8 residual blocks: x = x + LN(ReLU(x @ Wb[i] + bb[i]))
    for (int i = 0; i < NLAYER; i++) {
        sgemm_bias_act<<<gH, blk>>>(gx, Wb + (size_t)i * HDIM * HDIM,
                                    bb + (size_t)i * HDIM, gy,
                                    BSZ, HDIM, HDIM, 1);
        ln_res<<<BSZ, blk>>>(gy, gx, gb + (size_t)i * HDIM,
                             btb + (size_t)i * HDIM, gx, 1);
    }

    // out_transform: z = ReLU(x @ w1 + b1) @ w2 + b2
    sgemm_bias_act<<<gH, blk>>>(gx, w1, b1, gy, BSZ, HDIM, HDIM, 1);
    sgemm_bias_act<<<gE, blk>>>(gy, w2, b2, gz, BSZ, EDIM, HDIM, 0);

    // logits + mask
    logits_k<<<BSZ, blk>>>(gz, AE, idx, out);
}

// round 7
// speedup vs baseline: 2.1531x; 2.1531x over previous
#include <cuda_runtime.h>
#include <cuda_bf16.h>
#include <math.h>
#include <stdint.h>

// ---------------------------------------------------------------------------
// Problem constants
// ---------------------------------------------------------------------------
#define BSZ 16384
#define EDIM 256
#define HDIM 1024
#define NLAYER 8
#define NACT 256
#define NK 4
#define HH (HDIM * HDIM)

// Transposed/split weight offsets (elements)
#define W0T_OFF 0
#define WBT_OFF (EDIM * HDIM)
#define W1T_OFF (WBT_OFF + NLAYER * HH)
#define W2T_OFF (W1T_OFF + HH)
#define WT_TOTAL (W2T_OFF + HDIM * EDIM)

// ---------------------------------------------------------------------------
// Scratch (device globals — no allocation allowed)
// ---------------------------------------------------------------------------
__device__ __align__(128) float g_x[(size_t)BSZ * HDIM];
__device__ __align__(128) float g_y[(size_t)BSZ * HDIM];
__device__ __align__(128) float g_z[(size_t)BSZ * EDIM];
__device__ __align__(128) __nv_bfloat16 g_ahi[(size_t)BSZ * HDIM];
__device__ __align__(128) __nv_bfloat16 g_alo[(size_t)BSZ * HDIM];
__device__ __align__(128) __nv_bfloat16 g_bhi[(size_t)BSZ * HDIM];
__device__ __align__(128) __nv_bfloat16 g_blo[(size_t)BSZ * HDIM];
__device__ __align__(128) __nv_bfloat16 g_whi[WT_TOTAL];
__device__ __align__(128) __nv_bfloat16 g_wlo[WT_TOTAL];

// ---------------------------------------------------------------------------
// Helpers (all baseline PTX, no sm_103a-variant features)
// ---------------------------------------------------------------------------
static __device__ __forceinline__ uint32_t smem_u32(const void* p) {
    uint32_t a;
    asm("{ .reg .u64 t; cvta.to.shared.u64 t, %1; cvt.u32.u64 %0, t; }"
        : "=r"(a) : "l"(p));
    return a;
}

static __device__ __forceinline__ void cp16(uint32_t dst, const void* src) {
    asm volatile("cp.async.cg.shared.global [%0], [%1], 16;"
                 :: "r"(dst), "l"(src) : "memory");
}
static __device__ __forceinline__ void cp_commit() {
    asm volatile("cp.async.commit_group;" ::: "memory");
}
template <int N>
static __device__ __forceinline__ void cp_wait() {
    asm volatile("cp.async.wait_group %0;" :: "n"(N) : "memory");
}

static __device__ __forceinline__ void ldsm4(uint32_t* r, uint32_t addr) {
    asm volatile("ldmatrix.sync.aligned.m8n8.x4.shared.b16 {%0,%1,%2,%3}, [%4];"
                 : "=r"(r[0]), "=r"(r[1]), "=r"(r[2]), "=r"(r[3]) : "r"(addr));
}

static __device__ __forceinline__ void mma16816(float* c, const uint32_t* a,
                                                const uint32_t* b) {
    asm volatile(
        "mma.sync.aligned.m16n8k16.row.col.f32.bf16.bf16.f32 "
        "{%0,%1,%2,%3}, {%4,%5,%6,%7}, {%8,%9}, {%0,%1,%2,%3};"
        : "+f"(c[0]), "+f"(c[1]), "+f"(c[2]), "+f"(c[3])
        : "r"(a[0]), "r"(a[1]), "r"(a[2]), "r"(a[3]), "r"(b[0]), "r"(b[1]));
}

static __device__ __forceinline__ void split1(float v, float& hi, float& lo) {
    __nv_bfloat16 h = __float2bfloat16(v);
    float hf = __bfloat162float(h);
    hi = hf;
    lo = v - hf;
}
static __device__ __forceinline__ uint32_t pack_bf2(float a, float b) {
    union { __nv_bfloat162 b2; uint32_t u; } t;
    t.b2 = __floats2bfloat162_rn(a, b);
    return t.u;
}

// Swizzled smem offset for a 128-row x 32-bf16 (64B) tile.
// chunk c (16B units, 0..3), row r: physical chunk = c ^ ((r>>1)&3).
// Gives conflict-free ldmatrix (8 rows hit 8 distinct 16B segments of 128B).
static __device__ __forceinline__ uint32_t sw_off(int r, int c) {
    return ((uint32_t)r << 6) + (((uint32_t)(c ^ ((r >> 1) & 3))) << 4);
}

// ---------------------------------------------------------------------------
// HMMA split-bf16 GEMM: Y[M,N] = act((Ahi+Alo) @ (Bhi+Blo)^T + bias)
//   A: [M,K] row-major bf16 hi/lo.  B: [N,K] row-major bf16 hi/lo.
//   3 passes: AhBh + AhBl + AlBh (AlBl dropped).
//   CTA tile 128x128, BK=32, 256 threads (8 warps, each 32m x 64n),
//   cp.async 3-stage pipeline, fp32 accum in registers.
// ---------------------------------------------------------------------------
#define BKC 32
#define NSTG 3
#define TILEB 8192                 // 128 x 32 bf16
#define STGB (4 * TILEB)           // Ah, Al, Bh, Bl
#define GEMM_SMEM (NSTG * STGB)    // 96 KB

__global__ __launch_bounds__(256, 1)
void gemm_hmma(const __nv_bfloat16* __restrict__ Ahi, const __nv_bfloat16* __restrict__ Alo,
               const __nv_bfloat16* __restrict__ Bhi, const __nv_bfloat16* __restrict__ Blo,
               const float* __restrict__ bias, float* __restrict__ Y,
               __nv_bfloat16* __restrict__ Yhi, __nv_bfloat16* __restrict__ Ylo,
               int K, int N, int relu)
{
    extern __shared__ char dsm[];
    const uint32_t smem = smem_u32(dsm);

    const int tid = threadIdx.x;
    const int wid = tid >> 5, lid = tid & 31;
    const int m0 = blockIdx.y * 128;
    const int n0 = blockIdx.x * 128;
    const int wm = wid & 3;        // 0..3 -> 32-row slices
    const int wn = wid >> 2;       // 0..1 -> 64-col slices
    const int m0w = wm * 32;
    const int n0w = wn * 64;

    // Per-lane ldmatrix row/chunk components
    const int q  = lid >> 3;       // matrix index 0..3
    const int lr = lid & 7;        // row within 8x8 matrix
    const int a_row_add = (q & 1) * 8 + lr;   // + (q>>1) selects k-chunk
    const int a_chk_add = q >> 1;
    const int b_row_add = (q >> 1) * 8 + lr;  // + (q&1) selects k-chunk
    const int b_chk_add = q & 1;

    const int nchunk = K / BKC;

    // ---- stage loader: 8 cp.async (16B) per thread -> 32KB stage ----
    auto load_stage = [&](int j, int s) {
        const int k0 = j * BKC;
        const uint32_t sb = smem + (uint32_t)s * STGB;
#pragma unroll
        for (int t = 0; t < 2; t++) {
            const int idx = tid + t * 256;        // 0..511
            const int r = idx >> 2;               // 0..127
            const int c = idx & 3;                // 16B chunk
            const uint32_t so = sw_off(r, c);
            const size_t ga = (size_t)(m0 + r) * K + k0 + c * 8;
            const size_t gb = (size_t)(n0 + r) * K + k0 + c * 8;
            cp16(sb + so,             Ahi + ga);
            cp16(sb + TILEB + so,     Alo + ga);
            cp16(sb + 2 * TILEB + so, Bhi + gb);
            cp16(sb + 3 * TILEB + so, Blo + gb);
        }
        cp_commit();
    };

    float acc[2][8][4];
#pragma unroll
    for (int i = 0; i < 2; i++)
#pragma unroll
        for (int j = 0; j < 8; j++)
#pragma unroll
            for (int v = 0; v < 4; v++) acc[i][j][v] = 0.f;

    // Prologue: fill NSTG-1 stages
    load_stage(0, 0);
    load_stage(1, 1);

    for (int j = 0; j < nchunk; ++j) {
        cp_wait<NSTG - 2>();
        __syncthreads();

        // Prefetch next-next stage (overwrites buffer finished 2 iters ago)
        if (j + NSTG - 1 < nchunk)
            load_stage(j + NSTG - 1, (j + NSTG - 1) % NSTG);

        const uint32_t sb = smem + (uint32_t)(j % NSTG) * STGB;
        const uint32_t Ah = sb, Al = sb + TILEB;
        const uint32_t Bh = sb + 2 * TILEB, Bl = sb + 3 * TILEB;

#pragma unroll
        for (int kk = 0; kk < 2; kk++) {          // two k16 steps per BK=32
            const int kc = kk * 2;                // base 16B chunk of this k16
            uint32_t ah[2][4], al[2][4];
#pragma unroll
            for (int mt = 0; mt < 2; mt++) {
                const int row = m0w + mt * 16 + a_row_add;
                const uint32_t off = sw_off(row, kc + a_chk_add);
                ldsm4(ah[mt], Ah + off);
                ldsm4(al[mt], Al + off);
            }
            uint32_t bh[4][4], bl[4][4];          // each x4 = two n8 frags
#pragma unroll
            for (int np = 0; np < 4; np++) {
                const int row = n0w + np * 16 + b_row_add;
                const uint32_t off = sw_off(row, kc + b_chk_add);
                ldsm4(bh[np], Bh + off);
                ldsm4(bl[np], Bl + off);
            }
#pragma unroll
            for (int mt = 0; mt < 2; mt++) {
#pragma unroll
                for (int nt = 0; nt < 8; nt++) {
                    const uint32_t* ph = &bh[nt >> 1][(nt & 1) * 2];
                    const uint32_t* pl = &bl[nt >> 1][(nt & 1) * 2];
                    mma16816(acc[mt][nt], ah[mt], ph);
                    mma16816(acc[mt][nt], ah[mt], pl);
                    mma16816(acc[mt][nt], al[mt], ph);
                }
            }
        }
        __syncthreads();
    }

    // ---- epilogue: bias + relu + fp32 store (+ optional bf16 hi/lo split) ----
    const int lrow = lid >> 2;                 // 0..7
    const int lcol = (lid & 3) << 1;           // 0,2,4,6
#pragma unroll
    for (int mt = 0; mt < 2; mt++) {
#pragma unroll
        for (int nt = 0; nt < 8; nt++) {
            const int ncol = n0 + n0w + nt * 8 + lcol;
            const float2 bb = *(const float2*)&bias[ncol];
#pragma unroll
            for (int h = 0; h < 2; h++) {      // c0,c1 then c2,c3 (row +8)
                const int mrow = m0 + m0w + mt * 16 + lrow + h * 8;
                float vx = acc[mt][nt][h * 2 + 0] + bb.x;
                float vy = acc[mt][nt][h * 2 + 1] + bb.y;
                if (relu) { vx = fmaxf(vx, 0.f); vy = fmaxf(vy, 0.f); }
                const size_t off = (size_t)mrow * N + ncol;
                *(float2*)&Y[off] = make_float2(vx, vy);
                if (Yhi != nullptr) {
                    float h0, l0, h1, l1;
                    split1(vx, h0, l0); split1(vy, h1, l1);
                    *(uint32_t*)(Yhi + off) = pack_bf2(h0, h1);
                    *(uint32_t*)(Ylo + off) = pack_bf2(l0, l1);
                }
            }
        }
    }
}

// ---------------------------------------------------------------------------
// LayerNorm over H=1024 + fused bf16 hi/lo split of the output.
// out = (hasRes ? res : 0) + LN(pre)*g + beta ; outhi/outlo = split(out)
// ---------------------------------------------------------------------------
__global__ __launch_bounds__(256)
void ln_res(const float* __restrict__ pre, const float* __restrict__ res,
            const float* __restrict__ g, const float* __restrict__ beta,
            float* __restrict__ out,
            __nv_bfloat16* __restrict__ outhi, __nv_bfloat16* __restrict__ outlo,
            int hasRes)
{
    const size_t row = blockIdx.x;
    const int c = threadIdx.x << 2;

    float4 v = *(const float4*)&pre[row * HDIM + c];
    float s  = v.x + v.y + v.z + v.w;
    float ss = v.x * v.x + v.y * v.y + v.z * v.z + v.w * v.w;
#pragma unroll
    for (int o = 16; o; o >>= 1) {
        s  += __shfl_xor_sync(0xFFFFFFFFu, s, o);
        ss += __shfl_xor_sync(0xFFFFFFFFu, ss, o);
    }
    __shared__ float sh_s[8], sh_ss[8];
    const int warp = threadIdx.x >> 5, lane = threadIdx.x & 31;
    if (lane == 0) { sh_s[warp] = s; sh_ss[warp] = ss; }
    __syncthreads();
    float ts = 0.f, tss = 0.f;
#pragma unroll
    for (int w = 0; w < 8; w++) { ts += sh_s[w]; tss += sh_ss[w]; }

    const float mean = ts * (1.0f / HDIM);
    const float var  = tss * (1.0f / HDIM) - mean * mean;
    const float inv  = rsqrtf(var + 1e-5f);

    const float4 gg = *(const float4*)&g[c];
    const float4 bb = *(const float4*)&beta[c];
    float4 o4;
    o4.x = (v.x - mean) * inv * gg.x + bb.x;
    o4.y = (v.y - mean) * inv * gg.y + bb.y;
    o4.z = (v.z - mean) * inv * gg.z + bb.z;
    o4.w = (v.w - mean) * inv * gg.w + bb.w;
    if (hasRes) {
        const float4 r = *(const float4*)&res[row * HDIM + c];
        o4.x += r.x; o4.y += r.y; o4.z += r.z; o4.w += r.w;
    }
    *(float4*)&out[row * HDIM + c] = o4;

    float h0, l0, h1, l1, h2, l2, h3, l3;
    split1(o4.x, h0, l0); split1(o4.y, h1, l1);
    split1(o4.z, h2, l2); split1(o4.w, h3, l3);
    uint2 uh; uh.x = pack_bf2(h0, h1); uh.y = pack_bf2(h2, h3);
    uint2 ul; ul.x = pack_bf2(l0, l1); ul.y = pack_bf2(l2, l3);
    *(uint2*)(outhi + row * HDIM + c) = uh;
    *(uint2*)(outlo + row * HDIM + c) = ul;
}

// ---------------------------------------------------------------------------
// Elementwise fp32 -> bf16 hi/lo split (for obs input)
// ---------------------------------------------------------------------------
__global__ __launch_bounds__(256)
void split_f32(const float* __restrict__ in,
               __nv_bfloat16* __restrict__ hi, __nv_bfloat16* __restrict__ lo, int n4)
{
    const int i = blockIdx.x * blockDim.x + threadIdx.x;
    if (i >= n4) return;
    const float4 v = ((const float4*)in)[i];
    float h0, l0, h1, l1, h2, l2, h3, l3;
    split1(v.x, h0, l0); split1(v.y, h1, l1);
    split1(v.z, h2, l2); split1(v.w, h3, l3);
    uint2 uh; uh.x = pack_bf2(h0, h1); uh.y = pack_bf2(h2, h3);
    uint2 ul; ul.x = pack_bf2(l0, l1); ul.y = pack_bf2(l2, l3);
    ((uint2*)hi)[i] = uh;
    ((uint2*)lo)[i] = ul;
}

// ---------------------------------------------------------------------------
// Weight transpose + split: W[K,N] fp32 -> Thi/Tlo[N,K] bf16
// ---------------------------------------------------------------------------
__global__ __launch_bounds__(256)
void transpose_split(const float* __restrict__ W,
                     __nv_bfloat16* __restrict__ Thi, __nv_bfloat16* __restrict__ Tlo,
                     int K, int N)
{
    __shared__ float t[32][33];
    const int tx = threadIdx.x, ty = threadIdx.y;
    const int n = blockIdx.x * 32 + tx;
#pragma unroll
    for (int i = 0; i < 4; i++) {
        const int k = blockIdx.y * 32 + ty + i * 8;
        t[ty + i * 8][tx] = W[(size_t)k * N + n];
    }
    __syncthreads();
    const int ko = blockIdx.y * 32 + tx;
#pragma unroll
    for (int i = 0; i < 4; i++) {
        const int no = blockIdx.x * 32 + ty + i * 8;
        const float v = t[tx][ty + i * 8];
        float h, l;
        split1(v, h, l);
        Thi[(size_t)no * K + ko] = __float2bfloat16(h);
        Tlo[(size_t)no * K + ko] = __float2bfloat16(l);
    }
}

// ---------------------------------------------------------------------------
// logits[b,a] = dot(z[b,:], AE[b,a,:]) ; -inf where sum(idx[b,a,:])==0
// ---------------------------------------------------------------------------
__global__ __launch_bounds__(256)
void logits_k(const float* __restrict__ z, const float* __restrict__ AE,
              const int* __restrict__ idx, float* __restrict__ out)
{
    const size_t b = blockIdx.x;
    __shared__ float zs[EDIM];
    zs[threadIdx.x] = z[b * EDIM + threadIdx.x];
    __syncthreads();

    const int warp = threadIdx.x >> 5, lane = threadIdx.x & 31;
    const float* aeb = AE + b * (size_t)NACT * EDIM;
    const int c = lane << 2;

    for (int a = warp; a < NACT; a += 8) {
        const float* r = aeb + (size_t)a * EDIM;
        const float4 x0 = *(const float4*)&r[c];
        const float4 x1 = *(const float4*)&r[128 + c];
        float acc = x0.x * zs[c]           + x0.y * zs[c + 1]
                  + x0.z * zs[c + 2]       + x0.w * zs[c + 3]
                  + x1.x * zs[128 + c]     + x1.y * zs[128 + c + 1]
                  + x1.z * zs[128 + c + 2] + x1.w * zs[128 + c + 3];
#pragma unroll
        for (int o = 16; o; o >>= 1)
            acc += __shfl_xor_sync(0xFFFFFFFFu, acc, o);
        if (lane == 0) {
            const int4 ii = *(const int4*)&idx[(b * NACT + a) * NK];
            const int sum = ii.x + ii.y + ii.z + ii.w;
            out[b * NACT + a] = (sum == 0) ? -INFINITY : acc;
        }
    }
}

// ---------------------------------------------------------------------------
// kernel_launch
// ---------------------------------------------------------------------------
extern "C" void kernel_launch(void* const* d_in, const int* in_sizes, int n_in,
                              void* d_out, int out_size)
{
    const float* obs  = (const float*)d_in[0];
    const float* AE   = (const float*)d_in[1];
    const int*   aidx = (const int*)  d_in[2];
    const float* w0   = (const float*)d_in[3];
    const float* b0   = (const float*)d_in[4];
    const float* g0   = (const float*)d_in[5];
    const float* bt0  = (const float*)d_in[6];
    const float* Wb   = (const float*)d_in[7];
    const float* bb   = (const float*)d_in[8];
    const float* gb   = (const float*)d_in[9];
    const float* btb  = (const float*)d_in[10];
    const float* w1   = (const float*)d_in[11];
    const float* b1   = (const float*)d_in[12];
    const float* w2   = (const float*)d_in[13];
    const float* b2   = (const float*)d_in[14];
    float* out = (float*)d_out;

    void *px, *py, *pz, *pah, *pal, *pbh, *pbl, *pwh, *pwl;
    cudaGetSymbolAddress(&px, g_x);
    cudaGetSymbolAddress(&py, g_y);
    cudaGetSymbolAddress(&pz, g_z);
    cudaGetSymbolAddress(&pah, g_ahi);
    cudaGetSymbolAddress(&pal, g_alo);
    cudaGetSymbolAddress(&pbh, g_bhi);
    cudaGetSymbolAddress(&pbl, g_blo);
    cudaGetSymbolAddress(&pwh, g_whi);
    cudaGetSymbolAddress(&pwl, g_wlo);
    float* gx = (float*)px;
    float* gy = (float*)py;
    float* gz = (float*)pz;
    __nv_bfloat16* ahi = (__nv_bfloat16*)pah;
    __nv_bfloat16* alo = (__nv_bfloat16*)pal;
    __nv_bfloat16* bhi = (__nv_bfloat16*)pbh;
    __nv_bfloat16* blo = (__nv_bfloat16*)pbl;
    __nv_bfloat16* whi = (__nv_bfloat16*)pwh;
    __nv_bfloat16* wlo = (__nv_bfloat16*)pwl;

    cudaFuncSetAttribute(gemm_hmma, cudaFuncAttributeMaxDynamicSharedMemorySize, GEMM_SMEM);

    const dim3 tb(32, 8);
    // Weight transpose + split: W[K,N] -> Wt[N,K] hi/lo
    transpose_split<<<dim3(HDIM / 32, EDIM / 32), tb>>>(w0, whi + W0T_OFF, wlo + W0T_OFF, EDIM, HDIM);
    for (int i = 0; i < NLAYER; i++)
        transpose_split<<<dim3(HDIM / 32, HDIM / 32), tb>>>(
            Wb + (size_t)i * HH, whi + WBT_OFF + (size_t)i * HH,
            wlo + WBT_OFF + (size_t)i * HH, HDIM, HDIM);
    transpose_split<<<dim3(HDIM / 32, HDIM / 32), tb>>>(w1, whi + W1T_OFF, wlo + W1T_OFF, HDIM, HDIM);
    transpose_split<<<dim3(EDIM / 32, HDIM / 32), tb>>>(w2, whi + W2T_OFF, wlo + W2T_OFF, HDIM, EDIM);

    // obs -> hi/lo split (into b-buffers, free at this point)
    split_f32<<<(BSZ * EDIM / 4 + 255) / 256, 256>>>(obs, bhi, blo, BSZ * EDIM / 4);

    const dim3 gH(HDIM / 128, BSZ / 128);   // (8, 128)
    const dim3 gE(EDIM / 128, BSZ / 128);   // (2, 128)

    // obs_transform: y = ReLU(obs @ w0 + b0); x = LN(y) (+ split)
    gemm_hmma<<<gH, 256, GEMM_SMEM>>>(bhi, blo, whi + W0T_OFF, wlo + W0T_OFF,
                                      b0, gy, nullptr, nullptr, EDIM, HDIM, 1);
    ln_res<<<BSZ, 256>>>(gy, nullptr, g0, bt0, gx, ahi, alo, 0);

    // 8 residual blocks
    for (int i = 0; i < NLAYER; i++) {
        gemm_hmma<<<gH, 256, GEMM_SMEM>>>(ahi, alo,
                                          whi + WBT_OFF + (size_t)i * HH,
                                          wlo + WBT_OFF + (size_t)i * HH,
                                          bb + (size_t)i * HDIM, gy,
                                          nullptr, nullptr, HDIM, HDIM, 1);
        ln_res<<<BSZ, 256>>>(gy, gx, gb + (size_t)i * HDIM,
                             btb + (size_t)i * HDIM, gx, ahi, alo, 1);
    }

    // out_transform: y1 = ReLU(x @ w1 + b1) (split); z = y1 @ w2 + b2
    gemm_hmma<<<gH, 256, GEMM_SMEM>>>(ahi, alo, whi + W1T_OFF, wlo + W1T_OFF,
                                      b1, gy, bhi, blo, HDIM, HDIM, 1);
    gemm_hmma<<<gE, 256, GEMM_SMEM>>>(bhi, blo, whi + W2T_OFF, wlo + W2T_OFF,
                                      b2, gz, nullptr, nullptr, HDIM, EDIM, 0);

    // logits + mask
    logits_k<<<BSZ, 256>>>(gz, AE, aidx, out);
}

// round 9
// speedup vs baseline: 3.0125x; 1.3992x over previous
#include <cuda_runtime.h>
#include <cuda_fp16.h>
#include <math.h>
#include <stdint.h>

// ---------------------------------------------------------------------------
// Problem constants
// ---------------------------------------------------------------------------
#define BSZ 16384
#define EDIM 256
#define HDIM 1024
#define NLAYER 8
#define NACT 256
#define NK 4
#define HH (HDIM * HDIM)

// Transposed fp16 weight offsets (elements)
#define W0T_OFF 0
#define WBT_OFF (EDIM * HDIM)
#define W1T_OFF (WBT_OFF + NLAYER * HH)
#define W2T_OFF (W1T_OFF + HH)
#define WT_TOTAL (W2T_OFF + HDIM * EDIM)

// ---------------------------------------------------------------------------
// Scratch (device globals — no allocation allowed)
// ---------------------------------------------------------------------------
__device__ __align__(128) float g_x[(size_t)BSZ * HDIM];       // fp32 residual x
__device__ __align__(128) float g_z[(size_t)BSZ * EDIM];       // fp32 final embed
__device__ __align__(128) __half g_ahi[(size_t)BSZ * HDIM];
__device__ __align__(128) __half g_alo[(size_t)BSZ * HDIM];
__device__ __align__(128) __half g_bhi[(size_t)BSZ * HDIM];
__device__ __align__(128) __half g_blo[(size_t)BSZ * HDIM];
__device__ __align__(128) __half g_wh[WT_TOTAL];

// ---------------------------------------------------------------------------
// Helpers (all baseline PTX, no sm_103a-variant features)
// ---------------------------------------------------------------------------
static __device__ __forceinline__ uint32_t smem_u32(const void* p) {
    uint32_t a;
    asm("{ .reg .u64 t; cvta.to.shared.u64 t, %1; cvt.u32.u64 %0, t; }"
        : "=r"(a) : "l"(p));
    return a;
}

static __device__ __forceinline__ void cp16(uint32_t dst, const void* src) {
    asm volatile("cp.async.cg.shared.global [%0], [%1], 16;"
                 :: "r"(dst), "l"(src) : "memory");
}
static __device__ __forceinline__ void cp_commit() {
    asm volatile("cp.async.commit_group;" ::: "memory");
}
template <int N>
static __device__ __forceinline__ void cp_wait() {
    asm volatile("cp.async.wait_group %0;" :: "n"(N) : "memory");
}

static __device__ __forceinline__ void ldsm4(uint32_t* r, uint32_t addr) {
    asm volatile("ldmatrix.sync.aligned.m8n8.x4.shared.b16 {%0,%1,%2,%3}, [%4];"
                 : "=r"(r[0]), "=r"(r[1]), "=r"(r[2]), "=r"(r[3]) : "r"(addr));
}

static __device__ __forceinline__ void mma16816(float* c, const uint32_t* a,
                                                const uint32_t* b) {
    asm volatile(
        "mma.sync.aligned.m16n8k16.row.col.f32.f16.f16.f32 "
        "{%0,%1,%2,%3}, {%4,%5,%6,%7}, {%8,%9}, {%0,%1,%2,%3};"
        : "+f"(c[0]), "+f"(c[1]), "+f"(c[2]), "+f"(c[3])
        : "r"(a[0]), "r"(a[1]), "r"(a[2]), "r"(a[3]), "r"(b[0]), "r"(b[1]));
}

// fp32 -> fp16 hi/lo split (hi + lo reconstructs v to ~2^-22 relative)
static __device__ __forceinline__ void split1h(float v, __half& h, __half& l) {
    h = __float2half_rn(v);
    l = __float2half_rn(v - __half2float(h));
}
static __device__ __forceinline__ uint32_t pack_h2(__half a, __half b) {
    union { __half2 h2; uint32_t u; } t;
    t.h2 = __halves2half2(a, b);
    return t.u;
}

// Swizzled smem offset for a 128-row x 32-fp16 (64B) tile.
// chunk c (16B units, 0..3), row r: physical chunk = c ^ ((r>>1)&3).
static __device__ __forceinline__ uint32_t sw_off(int r, int c) {
    return ((uint32_t)r << 6) + (((uint32_t)(c ^ ((r >> 1) & 3))) << 4);
}

// ---------------------------------------------------------------------------
// HMMA 2-pass fp16 GEMM: Y[M,N] = act((Ahi+Alo) @ B^T + bias)
//   A: [M,K] row-major fp16 hi/lo.  B: [N,K] row-major fp16 (pre-transposed W).
//   2 passes: Ah@B + Al@B (error = fp16 rounding of B, ~7e-5 rel).
//   CTA tile 128x128, BK=32, 256 threads (8 warps, each 32m x 64n),
//   cp.async 3-stage pipeline, fp32 accum in registers, 2 CTAs/SM.
//   Output: fp32 Y (if non-null) and/or fp16 hi/lo split (if non-null).
// ---------------------------------------------------------------------------
#define BKC 32
#define NSTG 3
#define TILEB 8192                 // 128 x 32 fp16
#define STGB (3 * TILEB)           // Ah, Al, B
#define GEMM_SMEM (NSTG * STGB)    // 72 KB

__global__ __launch_bounds__(256, 2)
void gemm_hmma(const __half* __restrict__ Ahi, const __half* __restrict__ Alo,
               const __half* __restrict__ B,
               const float* __restrict__ bias, float* __restrict__ Y,
               __half* __restrict__ Yhi, __half* __restrict__ Ylo,
               int K, int N, int relu)
{
    extern __shared__ char dsm[];
    const uint32_t smem = smem_u32(dsm);

    const int tid = threadIdx.x;
    const int wid = tid >> 5, lid = tid & 31;
    const int m0 = blockIdx.y * 128;
    const int n0 = blockIdx.x * 128;
    const int wm = wid & 3;        // 0..3 -> 32-row slices
    const int wn = wid >> 2;       // 0..1 -> 64-col slices
    const int m0w = wm * 32;
    const int n0w = wn * 64;

    // Per-lane ldmatrix row/chunk components
    const int q  = lid >> 3;       // matrix index 0..3
    const int lr = lid & 7;        // row within 8x8 matrix
    const int a_row_add = (q & 1) * 8 + lr;
    const int a_chk_add = q >> 1;
    const int b_row_add = (q >> 1) * 8 + lr;
    const int b_chk_add = q & 1;

    const int nchunk = K / BKC;

    // ---- stage loader: 6 cp.async (16B) per thread -> 24KB stage ----
    auto load_stage = [&](int j, int s) {
        const int k0 = j * BKC;
        const uint32_t sb = smem + (uint32_t)s * STGB;
#pragma unroll
        for (int t = 0; t < 2; t++) {
            const int idx = tid + t * 256;        // 0..511
            const int r = idx >> 2;               // 0..127
            const int c = idx & 3;                // 16B chunk
            const uint32_t so = sw_off(r, c);
            const size_t ga = (size_t)(m0 + r) * K + k0 + c * 8;
            const size_t gb = (size_t)(n0 + r) * K + k0 + c * 8;
            cp16(sb + so,             Ahi + ga);
            cp16(sb + TILEB + so,     Alo + ga);
            cp16(sb + 2 * TILEB + so, B + gb);
        }
        cp_commit();
    };

    float acc[2][8][4];
#pragma unroll
    for (int i = 0; i < 2; i++)
#pragma unroll
        for (int j = 0; j < 8; j++)
#pragma unroll
            for (int v = 0; v < 4; v++) acc[i][j][v] = 0.f;

    // Prologue: fill NSTG-1 stages
    load_stage(0, 0);
    load_stage(1, 1);

    for (int j = 0; j < nchunk; ++j) {
        cp_wait<NSTG - 2>();
        __syncthreads();        // single sync per chunk (ring proof: prefetch
                                // below targets buffer consumed in iter j-1,
                                // which all warps finished before this sync)
        if (j + NSTG - 1 < nchunk)
            load_stage(j + NSTG - 1, (j + NSTG - 1) % NSTG);

        const uint32_t sb = smem + (uint32_t)(j % NSTG) * STGB;
        const uint32_t Ah = sb, Al = sb + TILEB, Bs = sb + 2 * TILEB;

#pragma unroll
        for (int kk = 0; kk < 2; kk++) {          // two k16 steps per BK=32
            const int kc = kk * 2;
            uint32_t ah[2][4], al[2][4];
#pragma unroll
            for (int mt = 0; mt < 2; mt++) {
                const int row = m0w + mt * 16 + a_row_add;
                const uint32_t off = sw_off(row, kc + a_chk_add);
                ldsm4(ah[mt], Ah + off);
                ldsm4(al[mt], Al + off);
            }
            uint32_t bh[4][4];
#pragma unroll
            for (int np = 0; np < 4; np++) {
                const int row = n0w + np * 16 + b_row_add;
                const uint32_t off = sw_off(row, kc + b_chk_add);
                ldsm4(bh[np], Bs + off);
            }
#pragma unroll
            for (int mt = 0; mt < 2; mt++) {
#pragma unroll
                for (int nt = 0; nt < 8; nt++) {
                    const uint32_t* pb = &bh[nt >> 1][(nt & 1) * 2];
                    mma16816(acc[mt][nt], ah[mt], pb);
                    mma16816(acc[mt][nt], al[mt], pb);
                }
            }
        }
    }

    // ---- epilogue: bias + relu; fp32 store and/or fp16 hi/lo split ----
    const int lrow = lid >> 2;
    const int lcol = (lid & 3) << 1;
#pragma unroll
    for (int mt = 0; mt < 2; mt++) {
#pragma unroll
        for (int nt = 0; nt < 8; nt++) {
            const int ncol = n0 + n0w + nt * 8 + lcol;
            const float2 bb = *(const float2*)&bias[ncol];
#pragma unroll
            for (int h = 0; h < 2; h++) {
                const int mrow = m0 + m0w + mt * 16 + lrow + h * 8;
                float vx = acc[mt][nt][h * 2 + 0] + bb.x;
                float vy = acc[mt][nt][h * 2 + 1] + bb.y;
                if (relu) { vx = fmaxf(vx, 0.f); vy = fmaxf(vy, 0.f); }
                const size_t off = (size_t)mrow * N + ncol;
                if (Y != nullptr)
                    *(float2*)&Y[off] = make_float2(vx, vy);
                if (Yhi != nullptr) {
                    __half h0, l0, h1, l1;
                    split1h(vx, h0, l0); split1h(vy, h1, l1);
                    *(uint32_t*)(Yhi + off) = pack_h2(h0, h1);
                    *(uint32_t*)(Ylo + off) = pack_h2(l0, l1);
                }
            }
        }
    }
}

// ---------------------------------------------------------------------------
// LayerNorm over H=1024 + fused fp16 hi/lo split of the output.
// Input y reconstructed from fp16 hi/lo pair.
// outx = (hasRes ? res : 0) + LN(y)*g + beta ; outhi/outlo = split(outx)
// ---------------------------------------------------------------------------
__global__ __launch_bounds__(256)
void ln_res(const __half* __restrict__ yh, const __half* __restrict__ yl,
            const float* __restrict__ res,
            const float* __restrict__ g, const float* __restrict__ beta,
            float* __restrict__ outx,
            __half* __restrict__ outhi, __half* __restrict__ outlo,
            int hasRes)
{
    const size_t row = blockIdx.x;
    const int c = threadIdx.x << 2;

    const uint2 uh = *(const uint2*)(yh + row * HDIM + c);
    const uint2 ul = *(const uint2*)(yl + row * HDIM + c);
    const __half2 h01 = *(const __half2*)&uh.x, h23 = *(const __half2*)&uh.y;
    const __half2 l01 = *(const __half2*)&ul.x, l23 = *(const __half2*)&ul.y;
    float4 v;
    v.x = __low2float(h01)  + __low2float(l01);
    v.y = __high2float(h01) + __high2float(l01);
    v.z = __low2float(h23)  + __low2float(l23);
    v.w = __high2float(h23) + __high2float(l23);

    float s  = v.x + v.y + v.z + v.w;
    float ss = v.x * v.x + v.y * v.y + v.z * v.z + v.w * v.w;
#pragma unroll
    for (int o = 16; o; o >>= 1) {
        s  += __shfl_xor_sync(0xFFFFFFFFu, s, o);
        ss += __shfl_xor_sync(0xFFFFFFFFu, ss, o);
    }
    __shared__ float sh_s[8], sh_ss[8];
    const int warp = threadIdx.x >> 5, lane = threadIdx.x & 31;
    if (lane == 0) { sh_s[warp] = s; sh_ss[warp] = ss; }
    __syncthreads();
    float ts = 0.f, tss = 0.f;
#pragma unroll
    for (int w = 0; w < 8; w++) { ts += sh_s[w]; tss += sh_ss[w]; }

    const float mean = ts * (1.0f / HDIM);
    const float var  = tss * (1.0f / HDIM) - mean * mean;
    const float inv  = rsqrtf(var + 1e-5f);

    const float4 gg = *(const float4*)&g[c];
    const float4 bb = *(const float4*)&beta[c];
    float4 o4;
    o4.x = (v.x - mean) * inv * gg.x + bb.x;
    o4.y = (v.y - mean) * inv * gg.y + bb.y;
    o4.z = (v.z - mean) * inv * gg.z + bb.z;
    o4.w = (v.w - mean) * inv * gg.w + bb.w;
    if (hasRes) {
        const float4 r = *(const float4*)&res[row * HDIM + c];
        o4.x += r.x; o4.y += r.y; o4.z += r.z; o4.w += r.w;
    }
    *(float4*)&outx[row * HDIM + c] = o4;

    __half h0, l0, h1, l1, h2, l2, h3, l3;
    split1h(o4.x, h0, l0); split1h(o4.y, h1, l1);
    split1h(o4.z, h2, l2); split1h(o4.w, h3, l3);
    uint2 oh; oh.x = pack_h2(h0, h1); oh.y = pack_h2(h2, h3);
    uint2 ol; ol.x = pack_h2(l0, l1); ol.y = pack_h2(l2, l3);
    *(uint2*)(outhi + row * HDIM + c) = oh;
    *(uint2*)(outlo + row * HDIM + c) = ol;
}

// ---------------------------------------------------------------------------
// Elementwise fp32 -> fp16 hi/lo split (for obs input)
// ---------------------------------------------------------------------------
__global__ __launch_bounds__(256)
void split_f32(const float* __restrict__ in,
               __half* __restrict__ hi, __half* __restrict__ lo, int n4)
{
    const int i = blockIdx.x * blockDim.x + threadIdx.x;
    if (i >= n4) return;
    const float4 v = ((const float4*)in)[i];
    __half h0, l0, h1, l1, h2, l2, h3, l3;
    split1h(v.x, h0, l0); split1h(v.y, h1, l1);
    split1h(v.z, h2, l2); split1h(v.w, h3, l3);
    uint2 uh; uh.x = pack_h2(h0, h1); uh.y = pack_h2(h2, h3);
    uint2 ul; ul.x = pack_h2(l0, l1); ul.y = pack_h2(l2, l3);
    ((uint2*)hi)[i] = uh;
    ((uint2*)lo)[i] = ul;
}

// ---------------------------------------------------------------------------
// Weight transpose: W[K,N] fp32 -> T[N,K] fp16
// ---------------------------------------------------------------------------
__global__ __launch_bounds__(256)
void transpose_half(const float* __restrict__ W, __half* __restrict__ T,
                    int K, int N)
{
    __shared__ float t[32][33];
    const int tx = threadIdx.x, ty = threadIdx.y;
    const int n = blockIdx.x * 32 + tx;
#pragma unroll
    for (int i = 0; i < 4; i++) {
        const int k = blockIdx.y * 32 + ty + i * 8;
        t[ty + i * 8][tx] = W[(size_t)k * N + n];
    }
    __syncthreads();
    const int ko = blockIdx.y * 32 + tx;
#pragma unroll
    for (int i = 0; i < 4; i++) {
        const int no = blockIdx.x * 32 + ty + i * 8;
        T[(size_t)no * K + ko] = __float2half_rn(t[tx][ty + i * 8]);
    }
}

// ---------------------------------------------------------------------------
// logits[b,a] = dot(z[b,:], AE[b,a,:]) ; -inf where sum(idx[b,a,:])==0
// Two actions per iteration for ILP (overlapped loads + shfl trees).
// ---------------------------------------------------------------------------
__global__ __launch_bounds__(256)
void logits_k(const float* __restrict__ z, const float* __restrict__ AE,
              const int* __restrict__ idx, float* __restrict__ out)
{
    const size_t b = blockIdx.x;
    __shared__ float zs[EDIM];
    zs[threadIdx.x] = z[b * EDIM + threadIdx.x];
    __syncthreads();

    const int warp = threadIdx.x >> 5, lane = threadIdx.x & 31;
    const float* aeb = AE + b * (size_t)NACT * EDIM;
    const int c = lane << 2;

    const float za0 = zs[c],       za1 = zs[c + 1];
    const float za2 = zs[c + 2],   za3 = zs[c + 3];
    const float zb0 = zs[128 + c],     zb1 = zs[128 + c + 1];
    const float zb2 = zs[128 + c + 2], zb3 = zs[128 + c + 3];

    for (int a0 = warp; a0 < NACT; a0 += 16) {
        const int a1 = a0 + 8;
        const float* r0 = aeb + (size_t)a0 * EDIM;
        const float* r1 = aeb + (size_t)a1 * EDIM;
        const float4 p0 = *(const float4*)&r0[c];
        const float4 p1 = *(const float4*)&r0[128 + c];
        const float4 q0 = *(const float4*)&r1[c];
        const float4 q1 = *(const float4*)&r1[128 + c];
        float acc0 = p0.x * za0 + p0.y * za1 + p0.z * za2 + p0.w * za3
                   + p1.x * zb0 + p1.y * zb1 + p1.z * zb2 + p1.w * zb3;
        float acc1 = q0.x * za0 + q0.y * za1 + q0.z * za2 + q0.w * za3
                   + q1.x * zb0 + q1.y * zb1 + q1.z * zb2 + q1.w * zb3;
#pragma unroll
        for (int o = 16; o; o >>= 1) {
            acc0 += __shfl_xor_sync(0xFFFFFFFFu, acc0, o);
            acc1 += __shfl_xor_sync(0xFFFFFFFFu, acc1, o);
        }
        if (lane == 0) {
            const int4 i0 = *(const int4*)&idx[(b * NACT + a0) * NK];
            const int4 i1 = *(const int4*)&idx[(b * NACT + a1) * NK];
            out[b * NACT + a0] =
                (i0.x + i0.y + i0.z + i0.w == 0) ? -INFINITY : acc0;
            out[b * NACT + a1] =
                (i1.x + i1.y + i1.z + i1.w == 0) ? -INFINITY : acc1;
        }
    }
}

// ---------------------------------------------------------------------------
// kernel_launch
// ---------------------------------------------------------------------------
extern "C" void kernel_launch(void* const* d_in, const int* in_sizes, int n_in,
                              void* d_out, int out_size)
{
    const float* obs  = (const float*)d_in[0];
    const float* AE   = (const float*)d_in[1];
    const int*   aidx = (const int*)  d_in[2];
    const float* w0   = (const float*)d_in[3];
    const float* b0   = (const float*)d_in[4];
    const float* g0   = (const float*)d_in[5];
    const float* bt0  = (const float*)d_in[6];
    const float* Wb   = (const float*)d_in[7];
    const float* bb   = (const float*)d_in[8];
    const float* gb   = (const float*)d_in[9];
    const float* btb  = (const float*)d_in[10];
    const float* w1   = (const float*)d_in[11];
    const float* b1   = (const float*)d_in[12];
    const float* w2   = (const float*)d_in[13];
    const float* b2   = (const float*)d_in[14];
    float* out = (float*)d_out;

    void *px, *pz, *pah, *pal, *pbh, *pbl, *pwh;
    cudaGetSymbolAddress(&px, g_x);
    cudaGetSymbolAddress(&pz, g_z);
    cudaGetSymbolAddress(&pah, g_ahi);
    cudaGetSymbolAddress(&pal, g_alo);
    cudaGetSymbolAddress(&pbh, g_bhi);
    cudaGetSymbolAddress(&pbl, g_blo);
    cudaGetSymbolAddress(&pwh, g_wh);
    float* gx = (float*)px;
    float* gz = (float*)pz;
    __half* ahi = (__half*)pah;
    __half* alo = (__half*)pal;
    __half* bhi = (__half*)pbh;
    __half* blo = (__half*)pbl;
    __half* wh  = (__half*)pwh;

    cudaFuncSetAttribute(gemm_hmma, cudaFuncAttributeMaxDynamicSharedMemorySize, GEMM_SMEM);

    const dim3 tb(32, 8);
    // Weight transpose to fp16: W[K,N] -> Wt[N,K]
    transpose_half<<<dim3(HDIM / 32, EDIM / 32), tb>>>(w0, wh + W0T_OFF, EDIM, HDIM);
    for (int i = 0; i < NLAYER; i++)
        transpose_half<<<dim3(HDIM / 32, HDIM / 32), tb>>>(
            Wb + (size_t)i * HH, wh + WBT_OFF + (size_t)i * HH, HDIM, HDIM);
    transpose_half<<<dim3(HDIM / 32, HDIM / 32), tb>>>(w1, wh + W1T_OFF, HDIM, HDIM);
    transpose_half<<<dim3(EDIM / 32, HDIM / 32), tb>>>(w2, wh + W2T_OFF, HDIM, EDIM);

    // obs -> fp16 hi/lo split (into a-buffers)
    split_f32<<<(BSZ * EDIM / 4 + 255) / 256, 256>>>(obs, ahi, alo, BSZ * EDIM / 4);

    const dim3 gH(HDIM / 128, BSZ / 128);   // (8, 128)
    const dim3 gE(EDIM / 128, BSZ / 128);   // (2, 128)

    // obs_transform: y = ReLU(obs @ w0 + b0) -> split only; x = LN(y) (+ split)
    gemm_hmma<<<gH, 256, GEMM_SMEM>>>(ahi, alo, wh + W0T_OFF, b0,
                                      nullptr, bhi, blo, EDIM, HDIM, 1);
    ln_res<<<BSZ, 256>>>(bhi, blo, nullptr, g0, bt0, gx, ahi, alo, 0);

    // 8 residual blocks
    for (int i = 0; i < NLAYER; i++) {
        gemm_hmma<<<gH, 256, GEMM_SMEM>>>(ahi, alo,
                                          wh + WBT_OFF + (size_t)i * HH,
                                          bb + (size_t)i * HDIM,
                                          nullptr, bhi, blo, HDIM, HDIM, 1);
        ln_res<<<BSZ, 256>>>(bhi, blo, gx, gb + (size_t)i * HDIM,
                             btb + (size_t)i * HDIM, gx, ahi, alo, 1);
    }

    // out_transform: y1 = ReLU(x @ w1 + b1) (split only); z = y1 @ w2 + b2 (fp32)
    gemm_hmma<<<gH, 256, GEMM_SMEM>>>(ahi, alo, wh + W1T_OFF, b1,
                                      nullptr, bhi, blo, HDIM, HDIM, 1);
    gemm_hmma<<<gE, 256, GEMM_SMEM>>>(bhi, blo, wh + W2T_OFF, b2,
                                      gz, nullptr, nullptr, HDIM, EDIM, 0);

    // logits + mask
    logits_k<<<BSZ, 256>>>(gz, AE, aidx, out);
}

// round 11
// speedup vs baseline: 3.0587x; 1.0154x over previous
#include <cuda_runtime.h>
#include <cuda_fp16.h>
#include <math.h>
#include <stdint.h>

// ---------------------------------------------------------------------------
// Problem constants
// ---------------------------------------------------------------------------
#define BSZ 16384
#define EDIM 256
#define HDIM 1024
#define NLAYER 8
#define NACT 256
#define NK 4
#define HH (HDIM * HDIM)

// Transposed fp16 weight offsets (elements)
#define W0T_OFF 0
#define WBT_OFF (EDIM * HDIM)
#define W1T_OFF (WBT_OFF + NLAYER * HH)
#define W2T_OFF (W1T_OFF + HH)
#define WT_TOTAL (W2T_OFF + HDIM * EDIM)

// ---------------------------------------------------------------------------
// Scratch (device globals — no allocation allowed)
// ---------------------------------------------------------------------------
__device__ __align__(128) float g_z[(size_t)BSZ * EDIM];       // fp32 final embed
__device__ __align__(128) __half g_ahi[(size_t)BSZ * HDIM];
__device__ __align__(128) __half g_alo[(size_t)BSZ * HDIM];
__device__ __align__(128) __half g_bhi[(size_t)BSZ * HDIM];
__device__ __align__(128) __half g_blo[(size_t)BSZ * HDIM];
__device__ __align__(128) __half g_wh[WT_TOTAL];

// ---------------------------------------------------------------------------
// Helpers (all baseline PTX, no sm_103a-variant features)
// ---------------------------------------------------------------------------
static __device__ __forceinline__ uint32_t smem_u32(const void* p) {
    uint32_t a;
    asm("{ .reg .u64 t; cvta.to.shared.u64 t, %1; cvt.u32.u64 %0, t; }"
        : "=r"(a) : "l"(p));
    return a;
}

static __device__ __forceinline__ void cp16(uint32_t dst, const void* src) {
    asm volatile("cp.async.cg.shared.global [%0], [%1], 16;"
                 :: "r"(dst), "l"(src) : "memory");
}
static __device__ __forceinline__ void cp_commit() {
    asm volatile("cp.async.commit_group;" ::: "memory");
}
template <int N>
static __device__ __forceinline__ void cp_wait() {
    asm volatile("cp.async.wait_group %0;" :: "n"(N) : "memory");
}

static __device__ __forceinline__ void ldsm4(uint32_t* r, uint32_t addr) {
    asm volatile("ldmatrix.sync.aligned.m8n8.x4.shared.b16 {%0,%1,%2,%3}, [%4];"
                 : "=r"(r[0]), "=r"(r[1]), "=r"(r[2]), "=r"(r[3]) : "r"(addr));
}

static __device__ __forceinline__ void mma16816(float* c, const uint32_t* a,
                                                const uint32_t* b) {
    asm volatile(
        "mma.sync.aligned.m16n8k16.row.col.f32.f16.f16.f32 "
        "{%0,%1,%2,%3}, {%4,%5,%6,%7}, {%8,%9}, {%0,%1,%2,%3};"
        : "+f"(c[0]), "+f"(c[1]), "+f"(c[2]), "+f"(c[3])
        : "r"(a[0]), "r"(a[1]), "r"(a[2]), "r"(a[3]), "r"(b[0]), "r"(b[1]));
}

// fp32 -> fp16 hi/lo split (hi + lo reconstructs v to ~2^-22 relative)
static __device__ __forceinline__ void split1h(float v, __half& h, __half& l) {
    h = __float2half_rn(v);
    l = __float2half_rn(v - __half2float(h));
}
static __device__ __forceinline__ uint32_t pack_h2(__half a, __half b) {
    union { __half2 h2; uint32_t u; } t;
    t.h2 = __halves2half2(a, b);
    return t.u;
}

// Swizzled smem offset for a 128-row x 32-fp16 (64B) tile.
// chunk c (16B units, 0..3), row r: physical chunk = c ^ ((r>>1)&3).
static __device__ __forceinline__ uint32_t sw_off(int r, int c) {
    return ((uint32_t)r << 6) + (((uint32_t)(c ^ ((r >> 1) & 3))) << 4);
}

// ---------------------------------------------------------------------------
// HMMA 2-pass fp16 GEMM: Y[M,N] = act((Ahi+Alo) @ B^T + bias)
//   A: [M,K] row-major fp16 hi/lo.  B: [N,K] row-major fp16 (pre-transposed W).
//   2 passes: Ah@B + Al@B.
//   CTA tile 128x128, BK=32, 256 threads (8 warps, each 32m x 64n),
//   cp.async 4-stage pipeline, fp32 accum in registers, 2 CTAs/SM.
// ---------------------------------------------------------------------------
#define BKC 32
#define NSTG 4
#define TILEB 8192                 // 128 x 32 fp16
#define STGB (3 * TILEB)           // Ah, Al, B
#define GEMM_SMEM (NSTG * STGB)    // 96 KB

__global__ __launch_bounds__(256, 2)
void gemm_hmma(const __half* __restrict__ Ahi, const __half* __restrict__ Alo,
               const __half* __restrict__ B,
               const float* __restrict__ bias, float* __restrict__ Y,
               __half* __restrict__ Yhi, __half* __restrict__ Ylo,
               int K, int N, int relu)
{
    extern __shared__ char dsm[];
    const uint32_t smem = smem_u32(dsm);

    const int tid = threadIdx.x;
    const int wid = tid >> 5, lid = tid & 31;
    const int m0 = blockIdx.y * 128;
    const int n0 = blockIdx.x * 128;
    const int wm = wid & 3;        // 0..3 -> 32-row slices
    const int wn = wid >> 2;       // 0..1 -> 64-col slices
    const int m0w = wm * 32;
    const int n0w = wn * 64;

    // Per-lane ldmatrix row/chunk components
    const int q  = lid >> 3;       // matrix index 0..3
    const int lr = lid & 7;        // row within 8x8 matrix
    const int a_row_add = (q & 1) * 8 + lr;
    const int a_chk_add = q >> 1;
    const int b_row_add = (q >> 1) * 8 + lr;
    const int b_chk_add = q & 1;

    const int nchunk = K / BKC;

    // ---- stage loader: 6 cp.async (16B) per thread -> 24KB stage ----
    auto load_stage = [&](int j, int s) {
        const int k0 = j * BKC;
        const uint32_t sb = smem + (uint32_t)s * STGB;
#pragma unroll
        for (int t = 0; t < 2; t++) {
            const int idx = tid + t * 256;        // 0..511
            const int r = idx >> 2;               // 0..127
            const int c = idx & 3;                // 16B chunk
            const uint32_t so = sw_off(r, c);
            const size_t ga = (size_t)(m0 + r) * K + k0 + c * 8;
            const size_t gb = (size_t)(n0 + r) * K + k0 + c * 8;
            cp16(sb + so,             Ahi + ga);
            cp16(sb + TILEB + so,     Alo + ga);
            cp16(sb + 2 * TILEB + so, B + gb);
        }
        cp_commit();
    };

    float acc[2][8][4];
#pragma unroll
    for (int i = 0; i < 2; i++)
#pragma unroll
        for (int j = 0; j < 8; j++)
#pragma unroll
            for (int v = 0; v < 4; v++) acc[i][j][v] = 0.f;

    // Prologue: fill NSTG-1 stages (nchunk >= 8 always)
    load_stage(0, 0);
    load_stage(1, 1);
    load_stage(2, 2);

    for (int j = 0; j < nchunk; ++j) {
        cp_wait<NSTG - 2>();
        __syncthreads();        // single sync per chunk: prefetch below targets
                                // the buffer consumed in iter j-1, which every
                                // warp finished before this barrier
        if (j + NSTG - 1 < nchunk)
            load_stage(j + NSTG - 1, (j + NSTG - 1) % NSTG);

        const uint32_t sb = smem + (uint32_t)(j % NSTG) * STGB;
        const uint32_t Ah = sb, Al = sb + TILEB, Bs = sb + 2 * TILEB;

#pragma unroll
        for (int kk = 0; kk < 2; kk++) {          // two k16 steps per BK=32
            const int kc = kk * 2;
            uint32_t ah[2][4], al[2][4];
#pragma unroll
            for (int mt = 0; mt < 2; mt++) {
                const int row = m0w + mt * 16 + a_row_add;
                const uint32_t off = sw_off(row, kc + a_chk_add);
                ldsm4(ah[mt], Ah + off);
                ldsm4(al[mt], Al + off);
            }
            uint32_t bh[4][4];
#pragma unroll
            for (int np = 0; np < 4; np++) {
                const int row = n0w + np * 16 + b_row_add;
                const uint32_t off = sw_off(row, kc + b_chk_add);
                ldsm4(bh[np], Bs + off);
            }
#pragma unroll
            for (int mt = 0; mt < 2; mt++) {
#pragma unroll
                for (int nt = 0; nt < 8; nt++) {
                    const uint32_t* pb = &bh[nt >> 1][(nt & 1) * 2];
                    mma16816(acc[mt][nt], ah[mt], pb);
                    mma16816(acc[mt][nt], al[mt], pb);
                }
            }
        }
    }

    // ---- epilogue: bias + relu; fp32 store and/or fp16 hi/lo split ----
    const int lrow = lid >> 2;
    const int lcol = (lid & 3) << 1;
#pragma unroll
    for (int mt = 0; mt < 2; mt++) {
#pragma unroll
        for (int nt = 0; nt < 8; nt++) {
            const int ncol = n0 + n0w + nt * 8 + lcol;
            const float2 bb = *(const float2*)&bias[ncol];
#pragma unroll
            for (int h = 0; h < 2; h++) {
                const int mrow = m0 + m0w + mt * 16 + lrow + h * 8;
                float vx = acc[mt][nt][h * 2 + 0] + bb.x;
                float vy = acc[mt][nt][h * 2 + 1] + bb.y;
                if (relu) { vx = fmaxf(vx, 0.f); vy = fmaxf(vy, 0.f); }
                const size_t off = (size_t)mrow * N + ncol;
                if (Y != nullptr)
                    *(float2*)&Y[off] = make_float2(vx, vy);
                if (Yhi != nullptr) {
                    __half h0, l0, h1, l1;
                    split1h(vx, h0, l0); split1h(vy, h1, l1);
                    *(uint32_t*)(Yhi + off) = pack_h2(h0, h1);
                    *(uint32_t*)(Ylo + off) = pack_h2(l0, l1);
                }
            }
        }
    }
}

// ---------------------------------------------------------------------------
// LayerNorm over H=1024, fully in fp16 hi/lo domain.
//   y  = yh + yl  (pre-LN activations)
//   x  = xh + xl  (residual, may alias outh/outl — in-place update)
//   out = (hasRes ? x : 0) + LN(y)*g + beta ; outh/outl = split(out)
// NOTE: xh/xl and outh/outl intentionally NOT __restrict__ (they alias).
// Each thread reads its own 4 elements before writing them; no cross-thread
// sharing of these arrays, so in-place is safe.
// ---------------------------------------------------------------------------
__global__ __launch_bounds__(256)
void ln_res(const __half* __restrict__ yh, const __half* __restrict__ yl,
            const __half* xh, const __half* xl,
            const float* __restrict__ g, const float* __restrict__ beta,
            __half* outh, __half* outl,
            int hasRes)
{
    const size_t row = blockIdx.x;
    const int c = threadIdx.x << 2;

    const uint2 uh = *(const uint2*)(yh + row * HDIM + c);
    const uint2 ul = *(const uint2*)(yl + row * HDIM + c);
    const __half2 h01 = *(const __half2*)&uh.x, h23 = *(const __half2*)&uh.y;
    const __half2 l01 = *(const __half2*)&ul.x, l23 = *(const __half2*)&ul.y;
    float4 v;
    v.x = __low2float(h01)  + __low2float(l01);
    v.y = __high2float(h01) + __high2float(l01);
    v.z = __low2float(h23)  + __low2float(l23);
    v.w = __high2float(h23) + __high2float(l23);

    // Residual read (before any writes to outh/outl which may alias xh/xl)
    float4 r4 = make_float4(0.f, 0.f, 0.f, 0.f);
    if (hasRes) {
        const uint2 rh = *(const uint2*)(xh + row * HDIM + c);
        const uint2 rl = *(const uint2*)(xl + row * HDIM + c);
        const __half2 rh01 = *(const __half2*)&rh.x, rh23 = *(const __half2*)&rh.y;
        const __half2 rl01 = *(const __half2*)&rl.x, rl23 = *(const __half2*)&rl.y;
        r4.x = __low2float(rh01)  + __low2float(rl01);
        r4.y = __high2float(rh01) + __high2float(rl01);
        r4.z = __low2float(rh23)  + __low2float(rl23);
        r4.w = __high2float(rh23) + __high2float(rl23);
    }

    float s  = v.x + v.y + v.z + v.w;
    float ss = v.x * v.x + v.y * v.y + v.z * v.z + v.w * v.w;
#pragma unroll
    for (int o = 16; o; o >>= 1) {
        s  += __shfl_xor_sync(0xFFFFFFFFu, s, o);
        ss += __shfl_xor_sync(0xFFFFFFFFu, ss, o);
    }
    __shared__ float sh_s[8], sh_ss[8];
    const int warp = threadIdx.x >> 5, lane = threadIdx.x & 31;
    if (lane == 0) { sh_s[warp] = s; sh_ss[warp] = ss; }
    __syncthreads();
    float ts = 0.f, tss = 0.f;
#pragma unroll
    for (int w = 0; w < 8; w++) { ts += sh_s[w]; tss += sh_ss[w]; }

    const float mean = ts * (1.0f / HDIM);
    const float var  = tss * (1.0f / HDIM) - mean * mean;
    const float inv  = rsqrtf(var + 1e-5f);

    const float4 gg = *(const float4*)&g[c];
    const float4 bb = *(const float4*)&beta[c];
    float4 o4;
    o4.x = (v.x - mean) * inv * gg.x + bb.x + r4.x;
    o4.y = (v.y - mean) * inv * gg.y + bb.y + r4.y;
    o4.z = (v.z - mean) * inv * gg.z + bb.z + r4.z;
    o4.w = (v.w - mean) * inv * gg.w + bb.w + r4.w;

    __half h0, l0, h1, l1, h2, l2, h3, l3;
    split1h(o4.x, h0, l0); split1h(o4.y, h1, l1);
    split1h(o4.z, h2, l2); split1h(o4.w, h3, l3);
    uint2 oh; oh.x = pack_h2(h0, h1); oh.y = pack_h2(h2, h3);
    uint2 ol; ol.x = pack_h2(l0, l1); ol.y = pack_h2(l2, l3);
    *(uint2*)(outh + row * HDIM + c) = oh;
    *(uint2*)(outl + row * HDIM + c) = ol;
}

// ---------------------------------------------------------------------------
// Elementwise fp32 -> fp16 hi/lo split (for obs input)
// ---------------------------------------------------------------------------
__global__ __launch_bounds__(256)
void split_f32(const float* __restrict__ in,
               __half* __restrict__ hi, __half* __restrict__ lo, int n4)
{
    const int i = blockIdx.x * blockDim.x + threadIdx.x;
    if (i >= n4) return;
    const float4 v = ((const float4*)in)[i];
    __half h0, l0, h1, l1, h2, l2, h3, l3;
    split1h(v.x, h0, l0); split1h(v.y, h1, l1);
    split1h(v.z, h2, l2); split1h(v.w, h3, l3);
    uint2 uh; uh.x = pack_h2(h0, h1); uh.y = pack_h2(h2, h3);
    uint2 ul; ul.x = pack_h2(l0, l1); ul.y = pack_h2(l2, l3);
    ((uint2*)hi)[i] = uh;
    ((uint2*)lo)[i] = ul;
}

// ---------------------------------------------------------------------------
// Weight transpose: W[K,N] fp32 -> T[N,K] fp16
// ---------------------------------------------------------------------------
__global__ __launch_bounds__(256)
void transpose_half(const float* __restrict__ W, __half* __restrict__ T,
                    int K, int N)
{
    __shared__ float t[32][33];
    const int tx = threadIdx.x, ty = threadIdx.y;
    const int n = blockIdx.x * 32 + tx;
#pragma unroll
    for (int i = 0; i < 4; i++) {
        const int k = blockIdx.y * 32 + ty + i * 8;
        t[ty + i * 8][tx] = W[(size_t)k * N + n];
    }
    __syncthreads();
    const int ko = blockIdx.y * 32 + tx;
#pragma unroll
    for (int i = 0; i < 4; i++) {
        const int no = blockIdx.x * 32 + ty + i * 8;
        T[(size_t)no * K + ko] = __float2half_rn(t[tx][ty + i * 8]);
    }
}

// ---------------------------------------------------------------------------
// logits[b,a] = dot(z[b,:], AE[b,a,:]) ; -inf where sum(idx[b,a,:])==0
// Two actions per iteration for ILP.
// ---------------------------------------------------------------------------
__global__ __launch_bounds__(256)
void logits_k(const float* __restrict__ z, const float* __restrict__ AE,
              const int* __restrict__ idx, float* __restrict__ out)
{
    const size_t b = blockIdx.x;
    __shared__ float zs[EDIM];
    zs[threadIdx.x] = z[b * EDIM + threadIdx.x];
    __syncthreads();

    const int warp = threadIdx.x >> 5, lane = threadIdx.x & 31;
    const float* aeb = AE + b * (size_t)NACT * EDIM;
    const int c = lane << 2;

    const float za0 = zs[c],       za1 = zs[c + 1];
    const float za2 = zs[c + 2],   za3 = zs[c + 3];
    const float zb0 = zs[128 + c],     zb1 = zs[128 + c + 1];
    const float zb2 = zs[128 + c + 2], zb3 = zs[128 + c + 3];

    for (int a0 = warp; a0 < NACT; a0 += 16) {
        const int a1 = a0 + 8;
        const float* r0 = aeb + (size_t)a0 * EDIM;
        const float* r1 = aeb + (size_t)a1 * EDIM;
        const float4 p0 = *(const float4*)&r0[c];
        const float4 p1 = *(const float4*)&r0[128 + c];
        const float4 q0 = *(const float4*)&r1[c];
        const float4 q1 = *(const float4*)&r1[128 + c];
        float acc0 = p0.x * za0 + p0.y * za1 + p0.z * za2 + p0.w * za3
                   + p1.x * zb0 + p1.y * zb1 + p1.z * zb2 + p1.w * zb3;
        float acc1 = q0.x * za0 + q0.y * za1 + q0.z * za2 + q0.w * za3
                   + q1.x * zb0 + q1.y * zb1 + q1.z * zb2 + q1.w * zb3;
#pragma unroll
        for (int o = 16; o; o >>= 1) {
            acc0 += __shfl_xor_sync(0xFFFFFFFFu, acc0, o);
            acc1 += __shfl_xor_sync(0xFFFFFFFFu, acc1, o);
        }
        if (lane == 0) {
            const int4 i0 = *(const int4*)&idx[(b * NACT + a0) * NK];
            const int4 i1 = *(const int4*)&idx[(b * NACT + a1) * NK];
            out[b * NACT + a0] =
                (i0.x + i0.y + i0.z + i0.w == 0) ? -INFINITY : acc0;
            out[b * NACT + a1] =
                (i1.x + i1.y + i1.z + i1.w == 0) ? -INFINITY : acc1;
        }
    }
}

// ---------------------------------------------------------------------------
// kernel_launch
// Launch order puts a K=1024 gemm_hmma at launch index 5 so ncu (-s 5 -c 1)
// profiles the dominant kernel.
// ---------------------------------------------------------------------------
extern "C" void kernel_launch(void* const* d_in, const int* in_sizes, int n_in,
                              void* d_out, int out_size)
{
    const float* obs  = (const float*)d_in[0];
    const float* AE   = (const float*)d_in[1];
    const int*   aidx = (const int*)  d_in[2];
    const float* w0   = (const float*)d_in[3];
    const float* b0   = (const float*)d_in[4];
    const float* g0   = (const float*)d_in[5];
    const float* bt0  = (const float*)d_in[6];
    const float* Wb   = (const float*)d_in[7];
    const float* bb   = (const float*)d_in[8];
    const float* gb   = (const float*)d_in[9];
    const float* btb  = (const float*)d_in[10];
    const float* w1   = (const float*)d_in[11];
    const float* b1   = (const float*)d_in[12];
    const float* w2   = (const float*)d_in[13];
    const float* b2   = (const float*)d_in[14];
    float* out = (float*)d_out;

    void *pz, *pah, *pal, *pbh, *pbl, *pwh;
    cudaGetSymbolAddress(&pz, g_z);
    cudaGetSymbolAddress(&pah, g_ahi);
    cudaGetSymbolAddress(&pal, g_alo);
    cudaGetSymbolAddress(&pbh, g_bhi);
    cudaGetSymbolAddress(&pbl, g_blo);
    cudaGetSymbolAddress(&pwh, g_wh);
    float* gz = (float*)pz;
    __half* ahi = (__half*)pah;
    __half* alo = (__half*)pal;
    __half* bhi = (__half*)pbh;
    __half* blo = (__half*)pbl;
    __half* wh  = (__half*)pwh;

    cudaFuncSetAttribute(gemm_hmma, cudaFuncAttributeMaxDynamicSharedMemorySize, GEMM_SMEM);

    const dim3 tb(32, 8);
    const dim3 gH(HDIM / 128, BSZ / 128);   // (8, 128)
    const dim3 gE(EDIM / 128, BSZ / 128);   // (2, 128)

    // 0: w0 transpose
    transpose_half<<<dim3(HDIM / 32, EDIM / 32), tb>>>(w0, wh + W0T_OFF, EDIM, HDIM);
    // 1: obs -> fp16 hi/lo split
    split_f32<<<(BSZ * EDIM / 4 + 255) / 256, 256>>>(obs, ahi, alo, BSZ * EDIM / 4);
    // 2: obs_transform gemm: y = ReLU(obs @ w0 + b0) -> (bhi, blo)
    gemm_hmma<<<gH, 256, GEMM_SMEM>>>(ahi, alo, wh + W0T_OFF, b0,
                                      nullptr, bhi, blo, EDIM, HDIM, 1);
    // 3: x = LN(y) -> (ahi, alo)
    ln_res<<<BSZ, 256>>>(bhi, blo, ahi, alo, g0, bt0, ahi, alo, 0);

    // Residual blocks (transpose interleaved so launch 5 is a K=1024 gemm)
    for (int i = 0; i < NLAYER; i++) {
        transpose_half<<<dim3(HDIM / 32, HDIM / 32), tb>>>(
            Wb + (size_t)i * HH, wh + WBT_OFF + (size_t)i * HH, HDIM, HDIM);
        gemm_hmma<<<gH, 256, GEMM_SMEM>>>(ahi, alo,
                                          wh + WBT_OFF + (size_t)i * HH,
                                          bb + (size_t)i * HDIM,
                                          nullptr, bhi, blo, HDIM, HDIM, 1);
        ln_res<<<BSZ, 256>>>(bhi, blo, ahi, alo, gb + (size_t)i * HDIM,
                             btb + (size_t)i * HDIM, ahi, alo, 1);
    }

    // out_transform: y1 = ReLU(x @ w1 + b1) -> (bhi, blo); z = y1 @ w2 + b2
    transpose_half<<<dim3(HDIM / 32, HDIM / 32), tb>>>(w1, wh + W1T_OFF, HDIM, HDIM);
    gemm_hmma<<<gH, 256, GEMM_SMEM>>>(ahi, alo, wh + W1T_OFF, b1,
                                      nullptr, bhi, blo, HDIM, HDIM, 1);
    transpose_half<<<dim3(EDIM / 32, HDIM / 32), tb>>>(w2, wh + W2T_OFF, HDIM, EDIM);
    gemm_hmma<<<gE, 256, GEMM_SMEM>>>(bhi, blo, wh + W2T_OFF, b2,
                                      gz, nullptr, nullptr, HDIM, EDIM, 0);

    // logits + mask
    logits_k<<<BSZ, 256>>>(gz, AE, aidx, out);
}